// round 1
// baseline (speedup 1.0000x reference)
#include <cuda_runtime.h>

// ---------------------------------------------------------------------------
// SGC: out = log_softmax( GC2( GC1(X) ) ),  GC(x) = S_in·Agg((S_out·x)W) + b
// Linear-collapse: W12 = W1@W2 applied BEFORE both aggregations.
//   Y = (S_out X) @ W12                      [N,40]
//   Z = Agg(Y)                               [N,40]   (scatter-add over edges)
//   g = Agg(dout_isqrt)                      [N]
//   U = Z * (dout_isqrt*din_isqrt)           [N,40]
//   V = Agg(U)                               [N,40]
//   out_pre = din_isqrt*(V + g*(b1@W2)) + b2
//   out = log_softmax(out_pre)
// ---------------------------------------------------------------------------

#define MAXN 50048
#define NF   40            // n_classes
#define INF_ 256           // in_feats
#define HID_ 128

__device__ float g_deg_out[MAXN];
__device__ float g_deg_in [MAXN];
__device__ float g_iso    [MAXN];     // dout^{-1/2}
__device__ float g_isi    [MAXN];     // din^{-1/2}
__device__ float g_gsum   [MAXN];     // Agg(dout_isqrt)
__device__ float g_W12    [INF_ * NF];
__device__ float g_cvec   [NF];       // b1 @ W2
__device__ float g_Y[50000 * NF];
__device__ float g_Z[50000 * NF];
__device__ float g_U[50000 * NF];
__device__ float g_V[50000 * NF];

// ---------------- zero scratch -------------------------------------------
__global__ void k_zero(int n) {
    int i = blockIdx.x * blockDim.x + threadIdx.x;
    int total = n * NF;
    if (i < total) { g_Z[i] = 0.f; g_V[i] = 0.f; }
    if (i < n)     { g_deg_out[i] = 0.f; g_deg_in[i] = 0.f; g_gsum[i] = 0.f; }
}

// ---------------- degrees -------------------------------------------------
__global__ void k_deg(const int* __restrict__ src, const int* __restrict__ dst, int E) {
    int e = blockIdx.x * blockDim.x + threadIdx.x;
    if (e >= E) return;
    atomicAdd(&g_deg_out[src[e]], 1.0f);
    atomicAdd(&g_deg_in [dst[e]], 1.0f);
}

__global__ void k_isqrt(int n) {
    int i = blockIdx.x * blockDim.x + threadIdx.x;
    if (i >= n) return;
    float dout = g_deg_out[i];
    float din  = g_deg_in[i];
    g_iso[i] = dout > 0.f ? rsqrtf(dout) : 0.f;
    g_isi[i] = din  > 0.f ? rsqrtf(din)  : 0.f;
}

// ---------------- W12 = W1 @ W2, cvec = b1 @ W2 ---------------------------
__global__ void k_w12(const float* __restrict__ W1, const float* __restrict__ W2,
                      const float* __restrict__ b1) {
    int idx = blockIdx.x * blockDim.x + threadIdx.x;   // 256*40 threads
    if (idx < INF_ * NF) {
        int r = idx / NF, c = idx - r * NF;
        float acc = 0.f;
        #pragma unroll 8
        for (int m = 0; m < HID_; m++)
            acc = fmaf(W1[r * HID_ + m], W2[m * NF + c], acc);
        g_W12[idx] = acc;
    }
    if (idx < NF) {
        float acc = 0.f;
        #pragma unroll 8
        for (int m = 0; m < HID_; m++)
            acc = fmaf(b1[m], W2[m * NF + idx], acc);
        g_cvec[idx] = acc;
    }
}

// ---------------- Y = (X * iso) @ W12  [N,256]@[256,40] -------------------
// TILE_M = 128 rows/block, 128 threads (16 x 8), thread tile = 8 rows x 5 cols.
#define GEMM_TM 128
#define KT 32
__global__ __launch_bounds__(128) void k_gemm(const float* __restrict__ X, int n) {
    __shared__ float As[KT * 132];          // [k][m], pitch 132 (16B-aligned rows)
    __shared__ float Bs[KT * NF];           // [k][c]
    const int t  = threadIdx.x;
    const int tr = t >> 3;                  // 0..15
    const int tc = t & 7;                   // 0..7
    const int m0 = blockIdx.x * GEMM_TM;

    float acc[8][5];
    #pragma unroll
    for (int i = 0; i < 8; i++)
        #pragma unroll
        for (int j = 0; j < 5; j++) acc[i][j] = 0.f;

    for (int k0 = 0; k0 < INF_; k0 += KT) {
        // load A tile: 128 rows x 32 k, coalesced in k
        #pragma unroll
        for (int i = 0; i < 32; i++) {
            int idx = i * 128 + t;
            int m = idx >> 5;               // 0..127
            int k = idx & 31;
            int row = m0 + m;
            float v = 0.f;
            if (row < n) v = X[row * INF_ + k0 + k] * g_iso[row];
            As[k * 132 + m] = v;
        }
        // load B tile: 32 x 40
        #pragma unroll
        for (int i = 0; i < 10; i++) {
            int idx = i * 128 + t;
            int k = idx / NF, c = idx - k * NF;
            Bs[k * NF + c] = g_W12[(k0 + k) * NF + c];
        }
        __syncthreads();

        #pragma unroll
        for (int k = 0; k < KT; k++) {
            float4 a0 = *(const float4*)&As[k * 132 + tr * 8];
            float4 a1 = *(const float4*)&As[k * 132 + tr * 8 + 4];
            float a[8] = {a0.x, a0.y, a0.z, a0.w, a1.x, a1.y, a1.z, a1.w};
            float b[5];
            #pragma unroll
            for (int j = 0; j < 5; j++) b[j] = Bs[k * NF + tc * 5 + j];
            #pragma unroll
            for (int i = 0; i < 8; i++)
                #pragma unroll
                for (int j = 0; j < 5; j++)
                    acc[i][j] = fmaf(a[i], b[j], acc[i][j]);
        }
        __syncthreads();
    }

    #pragma unroll
    for (int i = 0; i < 8; i++) {
        int row = m0 + tr * 8 + i;
        if (row < n) {
            #pragma unroll
            for (int j = 0; j < 5; j++)
                g_Y[row * NF + tc * 5 + j] = acc[i][j];
        }
    }
}

// ---------------- edge scatter: out[dst] += feat[src]  (40 f32 / edge) ----
// 10 threads per edge, float4 each. mode 0: Y->Z (+fused g). mode 1: U->V.
__global__ void k_scatter(const int* __restrict__ src, const int* __restrict__ dst,
                          int E, int mode) {
    int idx = blockIdx.x * blockDim.x + threadIdx.x;
    int e = idx / 10;
    int q = idx - e * 10;
    if (e >= E) return;
    int s = src[e];
    int d = dst[e];
    const float* fin = (mode == 0) ? g_Y : g_U;
    float*       fou = (mode == 0) ? g_Z : g_V;
    float4 v = *(const float4*)(fin + s * NF + q * 4);
    float* o = fou + d * NF + q * 4;
    atomicAdd(o + 0, v.x);
    atomicAdd(o + 1, v.y);
    atomicAdd(o + 2, v.z);
    atomicAdd(o + 3, v.w);
    if (mode == 0 && q == 0) atomicAdd(&g_gsum[d], g_iso[s]);
}

// ---------------- U = Z * iso * isi ---------------------------------------
__global__ void k_u(int n) {
    int idx = blockIdx.x * blockDim.x + threadIdx.x;
    if (idx >= n * NF) return;
    int node = idx / NF;
    g_U[idx] = g_Z[idx] * (g_iso[node] * g_isi[node]);
}

// ---------------- final: bias + rank-1 b1 term + log_softmax --------------
__global__ void k_final(const float* __restrict__ b2, float* __restrict__ out, int n) {
    int warp = (blockIdx.x * blockDim.x + threadIdx.x) >> 5;
    int lane = threadIdx.x & 31;
    if (warp >= n) return;
    float isi = g_isi[warp];
    float gs  = g_gsum[warp];
    const float NEG_INF = __int_as_float(0xff800000u);

    int c2 = lane + 32;
    float v1 = isi * g_V[warp * NF + lane] + isi * gs * g_cvec[lane] + b2[lane];
    float v2 = NEG_INF;
    if (c2 < NF)
        v2 = isi * g_V[warp * NF + c2] + isi * gs * g_cvec[c2] + b2[c2];

    float m = fmaxf(v1, v2);
    #pragma unroll
    for (int o = 16; o; o >>= 1) m = fmaxf(m, __shfl_xor_sync(0xffffffffu, m, o));

    float ssum = expf(v1 - m) + ((c2 < NF) ? expf(v2 - m) : 0.f);
    #pragma unroll
    for (int o = 16; o; o >>= 1) ssum += __shfl_xor_sync(0xffffffffu, ssum, o);

    float l = m + logf(ssum);
    out[warp * NF + lane] = v1 - l;
    if (c2 < NF) out[warp * NF + c2] = v2 - l;
}

// ---------------------------------------------------------------------------
extern "C" void kernel_launch(void* const* d_in, const int* in_sizes, int n_in,
                              void* d_out, int out_size) {
    const float* X   = (const float*)d_in[0];
    const int*   src = (const int*)  d_in[1];
    const int*   dst = (const int*)  d_in[2];
    const float* W1  = (const float*)d_in[3];
    const float* b1  = (const float*)d_in[4];
    const float* W2  = (const float*)d_in[5];
    const float* b2  = (const float*)d_in[6];
    float* out = (float*)d_out;

    const int N = in_sizes[0] / INF_;
    const int E = in_sizes[1];

    k_zero <<<(N * NF + 255) / 256, 256>>>(N);
    k_deg  <<<(E + 255) / 256, 256>>>(src, dst, E);
    k_isqrt<<<(N + 255) / 256, 256>>>(N);
    k_w12  <<<(INF_ * NF + 255) / 256, 256>>>(W1, W2, b1);
    k_gemm <<<(N + GEMM_TM - 1) / GEMM_TM, 128>>>(X, N);
    k_scatter<<<(E * 10 + 255) / 256, 256>>>(src, dst, E, 0);
    k_u    <<<(N * NF + 255) / 256, 256>>>(N);
    k_scatter<<<(E * 10 + 255) / 256, 256>>>(src, dst, E, 1);
    k_final<<<(N + 7) / 8, 256>>>(b2, out, N);
}

// round 2
// speedup vs baseline: 1.7597x; 1.7597x over previous
#include <cuda_runtime.h>

// ---------------------------------------------------------------------------
// SGC linear-collapse + CSR gather aggregation (no feature atomics).
//   W12 = W1@W2, cvec = b1@W2
//   Y = (X*iso) @ W12                          [N,40]
//   CSR-by-dst:  Z[d] = sum_{e: dst=d} Y[src[e]],  gsum[d] = sum iso[src]
//   V[d] = sum_{e: dst=d} Z[src]*scale[src],   scale = iso*isi
//   out = log_softmax( isi*(V + gsum*cvec) + b2 )
// ---------------------------------------------------------------------------

#define MAXN 50048
#define NF   40
#define INF_ 256
#define HID_ 128
#define MAXE 1600000

__device__ int   g_degi_out[MAXN];
__device__ int   g_degi_in [MAXN];
__device__ int   g_cursor  [MAXN];
__device__ int   g_rowstart[MAXN + 1];
__device__ int   g_csr     [MAXE];
__device__ float g_iso     [MAXN];
__device__ float g_isi     [MAXN];
__device__ float g_scale   [MAXN];
__device__ float g_gsum    [MAXN];
__device__ float g_W12     [INF_ * NF];
__device__ float g_cvec    [NF];
__device__ float g_Y[50000 * NF];
__device__ float g_Z[50000 * NF];
__device__ float g_V[50000 * NF];

// ---------------- zero counters -------------------------------------------
__global__ void k_zero(int n) {
    int i = blockIdx.x * blockDim.x + threadIdx.x;
    if (i < n) { g_degi_out[i] = 0; g_degi_in[i] = 0; g_cursor[i] = 0; }
}

// ---------------- degrees (int histogram) ---------------------------------
__global__ void k_deg(const int* __restrict__ src, const int* __restrict__ dst, int E) {
    int e = blockIdx.x * blockDim.x + threadIdx.x;
    if (e >= E) return;
    atomicAdd(&g_degi_out[src[e]], 1);
    atomicAdd(&g_degi_in [dst[e]], 1);
}

// ---------------- exclusive scan of deg_in -> rowstart (1 block) ----------
__global__ __launch_bounds__(1024) void k_scan(int n) {
    __shared__ int warpsum[32];
    __shared__ int chunk_total;
    int lane = threadIdx.x & 31, wid = threadIdx.x >> 5;
    if (threadIdx.x == 0) g_rowstart[0] = 0;
    int off = 0;
    for (int base = 0; base < n; base += 1024) {
        int i = base + threadIdx.x;
        int x = (i < n) ? g_degi_in[i] : 0;
        #pragma unroll
        for (int d = 1; d < 32; d <<= 1) {
            int t = __shfl_up_sync(0xffffffffu, x, d);
            if (lane >= d) x += t;
        }
        if (lane == 31) warpsum[wid] = x;
        __syncthreads();
        if (wid == 0) {
            int w = warpsum[lane];
            #pragma unroll
            for (int d = 1; d < 32; d <<= 1) {
                int t = __shfl_up_sync(0xffffffffu, w, d);
                if (lane >= d) w += t;
            }
            warpsum[lane] = w;
            if (lane == 31) chunk_total = w;
        }
        __syncthreads();
        int incl = x + (wid > 0 ? warpsum[wid - 1] : 0);
        if (i < n) g_rowstart[i + 1] = off + incl;
        off += chunk_total;
        __syncthreads();
    }
}

// ---------------- place edges into CSR slots -------------------------------
__global__ void k_place(const int* __restrict__ src, const int* __restrict__ dst, int E) {
    int e = blockIdx.x * blockDim.x + threadIdx.x;
    if (e >= E) return;
    int d = dst[e];
    int slot = g_rowstart[d] + atomicAdd(&g_cursor[d], 1);
    g_csr[slot] = src[e];
}

// ---------------- isqrt + scale --------------------------------------------
__global__ void k_isqrt(int n) {
    int i = blockIdx.x * blockDim.x + threadIdx.x;
    if (i >= n) return;
    float dout = (float)g_degi_out[i];
    float din  = (float)g_degi_in[i];
    float iso = dout > 0.f ? rsqrtf(dout) : 0.f;
    float isi = din  > 0.f ? rsqrtf(din)  : 0.f;
    g_iso[i] = iso;
    g_isi[i] = isi;
    g_scale[i] = iso * isi;
}

// ---------------- W12 = W1 @ W2, cvec = b1 @ W2 ----------------------------
__global__ __launch_bounds__(64) void k_w12(const float* __restrict__ W1,
                                            const float* __restrict__ W2,
                                            const float* __restrict__ b1) {
    int idx = blockIdx.x * 64 + threadIdx.x;
    if (idx < INF_ * NF) {
        int r = idx / NF, c = idx - r * NF;
        const float* w1 = W1 + r * HID_;
        const float* w2 = W2 + c;
        float a0 = 0.f, a1 = 0.f, a2 = 0.f, a3 = 0.f;
        #pragma unroll
        for (int m = 0; m < HID_; m += 4) {
            a0 = fmaf(__ldg(w1 + m + 0), __ldg(w2 + (m + 0) * NF), a0);
            a1 = fmaf(__ldg(w1 + m + 1), __ldg(w2 + (m + 1) * NF), a1);
            a2 = fmaf(__ldg(w1 + m + 2), __ldg(w2 + (m + 2) * NF), a2);
            a3 = fmaf(__ldg(w1 + m + 3), __ldg(w2 + (m + 3) * NF), a3);
        }
        g_W12[idx] = (a0 + a1) + (a2 + a3);
    }
    if (idx < NF) {
        float a0 = 0.f, a1 = 0.f;
        #pragma unroll
        for (int m = 0; m < HID_; m += 2) {
            a0 = fmaf(b1[m], W2[m * NF + idx], a0);
            a1 = fmaf(b1[m + 1], W2[(m + 1) * NF + idx], a1);
        }
        g_cvec[idx] = a0 + a1;
    }
}

// ---------------- Y = (X*iso) @ W12 with f32x2 packed FMA ------------------
#define GEMM_TM 128
#define KT 32
__global__ __launch_bounds__(128) void k_gemm(const float* __restrict__ X, int n) {
    __shared__ float  As[KT * 132];          // [k][m], pitch 132
    __shared__ float2 Bs2[KT * NF];          // duplicated pairs (b,b)
    const int t  = threadIdx.x;
    const int tr = t >> 3;                   // 0..15 -> 8 rows each
    const int tc = t & 7;                    // 0..7  -> 5 cols each
    const int m0 = blockIdx.x * GEMM_TM;

    unsigned long long acc[4][5];            // f32x2: rows (2p,2p+1) x col j
    #pragma unroll
    for (int p = 0; p < 4; p++)
        #pragma unroll
        for (int j = 0; j < 5; j++) acc[p][j] = 0ull;

    for (int k0 = 0; k0 < INF_; k0 += KT) {
        #pragma unroll
        for (int i = 0; i < 32; i++) {
            int idx = i * 128 + t;
            int m = idx >> 5;
            int k = idx & 31;
            int row = m0 + m;
            float v = 0.f;
            if (row < n) v = X[row * INF_ + k0 + k] * g_iso[row];
            As[k * 132 + m] = v;
        }
        #pragma unroll
        for (int i = 0; i < 10; i++) {
            int idx = i * 128 + t;
            int k = idx / NF, c = idx - k * NF;
            float w = g_W12[(k0 + k) * NF + c];
            Bs2[k * NF + c] = make_float2(w, w);
        }
        __syncthreads();

        #pragma unroll
        for (int k = 0; k < KT; k++) {
            float4 a0 = *(const float4*)&As[k * 132 + tr * 8];
            float4 a1 = *(const float4*)&As[k * 132 + tr * 8 + 4];
            unsigned long long pa[4];
            asm("mov.b64 %0, {%1, %2};" : "=l"(pa[0]) : "r"(__float_as_uint(a0.x)), "r"(__float_as_uint(a0.y)));
            asm("mov.b64 %0, {%1, %2};" : "=l"(pa[1]) : "r"(__float_as_uint(a0.z)), "r"(__float_as_uint(a0.w)));
            asm("mov.b64 %0, {%1, %2};" : "=l"(pa[2]) : "r"(__float_as_uint(a1.x)), "r"(__float_as_uint(a1.y)));
            asm("mov.b64 %0, {%1, %2};" : "=l"(pa[3]) : "r"(__float_as_uint(a1.z)), "r"(__float_as_uint(a1.w)));
            unsigned long long bb[5];
            #pragma unroll
            for (int j = 0; j < 5; j++)
                bb[j] = *(const unsigned long long*)&Bs2[k * NF + tc * 5 + j];
            #pragma unroll
            for (int p = 0; p < 4; p++)
                #pragma unroll
                for (int j = 0; j < 5; j++)
                    asm("fma.rn.f32x2 %0, %1, %2, %3;"
                        : "=l"(acc[p][j]) : "l"(pa[p]), "l"(bb[j]), "l"(acc[p][j]));
        }
        __syncthreads();
    }

    #pragma unroll
    for (int p = 0; p < 4; p++) {
        int row_lo = m0 + tr * 8 + 2 * p;
        #pragma unroll
        for (int j = 0; j < 5; j++) {
            unsigned int lo, hi;
            asm("mov.b64 {%0, %1}, %2;" : "=r"(lo), "=r"(hi) : "l"(acc[p][j]));
            if (row_lo < n)     g_Y[row_lo * NF + tc * 5 + j]       = __uint_as_float(lo);
            if (row_lo + 1 < n) g_Y[(row_lo + 1) * NF + tc * 5 + j] = __uint_as_float(hi);
        }
    }
}

// ---------------- CSR gather aggregation (10 threads/node, float4 each) ----
// mode 0: Z[d] = sum Y[src], gsum[d] = sum iso[src]
// mode 1: V[d] = sum Z[src]*scale[src]
__global__ __launch_bounds__(320) void k_agg(int n, int mode) {
    int idx = blockIdx.x * blockDim.x + threadIdx.x;
    int node = idx / 10;
    int q = idx - node * 10;
    if (node >= n) return;
    int beg = g_rowstart[node];
    int end = g_rowstart[node + 1];

    float4 acc0 = make_float4(0.f, 0.f, 0.f, 0.f);
    float4 acc1 = make_float4(0.f, 0.f, 0.f, 0.f);
    int e = beg;

    if (mode == 0) {
        float gs0 = 0.f, gs1 = 0.f;
        for (; e + 2 <= end; e += 2) {
            int s0 = g_csr[e], s1 = g_csr[e + 1];
            float4 v0 = *(const float4*)(g_Y + s0 * NF + q * 4);
            float4 v1 = *(const float4*)(g_Y + s1 * NF + q * 4);
            acc0.x += v0.x; acc0.y += v0.y; acc0.z += v0.z; acc0.w += v0.w;
            acc1.x += v1.x; acc1.y += v1.y; acc1.z += v1.z; acc1.w += v1.w;
            if (q == 0) { gs0 += g_iso[s0]; gs1 += g_iso[s1]; }
        }
        if (e < end) {
            int s = g_csr[e];
            float4 v = *(const float4*)(g_Y + s * NF + q * 4);
            acc0.x += v.x; acc0.y += v.y; acc0.z += v.z; acc0.w += v.w;
            if (q == 0) gs0 += g_iso[s];
        }
        if (q == 0) g_gsum[node] = gs0 + gs1;
        float4 r = make_float4(acc0.x + acc1.x, acc0.y + acc1.y,
                               acc0.z + acc1.z, acc0.w + acc1.w);
        *(float4*)(g_Z + node * NF + q * 4) = r;
    } else {
        for (; e + 2 <= end; e += 2) {
            int s0 = g_csr[e], s1 = g_csr[e + 1];
            float sc0 = g_scale[s0], sc1 = g_scale[s1];
            float4 v0 = *(const float4*)(g_Z + s0 * NF + q * 4);
            float4 v1 = *(const float4*)(g_Z + s1 * NF + q * 4);
            acc0.x = fmaf(v0.x, sc0, acc0.x); acc0.y = fmaf(v0.y, sc0, acc0.y);
            acc0.z = fmaf(v0.z, sc0, acc0.z); acc0.w = fmaf(v0.w, sc0, acc0.w);
            acc1.x = fmaf(v1.x, sc1, acc1.x); acc1.y = fmaf(v1.y, sc1, acc1.y);
            acc1.z = fmaf(v1.z, sc1, acc1.z); acc1.w = fmaf(v1.w, sc1, acc1.w);
        }
        if (e < end) {
            int s = g_csr[e];
            float sc = g_scale[s];
            float4 v = *(const float4*)(g_Z + s * NF + q * 4);
            acc0.x = fmaf(v.x, sc, acc0.x); acc0.y = fmaf(v.y, sc, acc0.y);
            acc0.z = fmaf(v.z, sc, acc0.z); acc0.w = fmaf(v.w, sc, acc0.w);
        }
        float4 r = make_float4(acc0.x + acc1.x, acc0.y + acc1.y,
                               acc0.z + acc1.z, acc0.w + acc1.w);
        *(float4*)(g_V + node * NF + q * 4) = r;
    }
}

// ---------------- final: bias + rank-1 b1 term + log_softmax ---------------
__global__ void k_final(const float* __restrict__ b2, float* __restrict__ out, int n) {
    int warp = (blockIdx.x * blockDim.x + threadIdx.x) >> 5;
    int lane = threadIdx.x & 31;
    if (warp >= n) return;
    float isi = g_isi[warp];
    float gs  = g_gsum[warp];
    const float NEG_INF = __int_as_float(0xff800000u);

    int c2 = lane + 32;
    float v1 = isi * g_V[warp * NF + lane] + isi * gs * g_cvec[lane] + b2[lane];
    float v2 = NEG_INF;
    if (c2 < NF)
        v2 = isi * g_V[warp * NF + c2] + isi * gs * g_cvec[c2] + b2[c2];

    float m = fmaxf(v1, v2);
    #pragma unroll
    for (int o = 16; o; o >>= 1) m = fmaxf(m, __shfl_xor_sync(0xffffffffu, m, o));

    float ssum = expf(v1 - m) + ((c2 < NF) ? expf(v2 - m) : 0.f);
    #pragma unroll
    for (int o = 16; o; o >>= 1) ssum += __shfl_xor_sync(0xffffffffu, ssum, o);

    float l = m + logf(ssum);
    out[warp * NF + lane] = v1 - l;
    if (c2 < NF) out[warp * NF + c2] = v2 - l;
}

// ---------------------------------------------------------------------------
extern "C" void kernel_launch(void* const* d_in, const int* in_sizes, int n_in,
                              void* d_out, int out_size) {
    const float* X   = (const float*)d_in[0];
    const int*   src = (const int*)  d_in[1];
    const int*   dst = (const int*)  d_in[2];
    const float* W1  = (const float*)d_in[3];
    const float* b1  = (const float*)d_in[4];
    const float* W2  = (const float*)d_in[5];
    const float* b2  = (const float*)d_in[6];
    float* out = (float*)d_out;

    const int N = in_sizes[0] / INF_;
    const int E = in_sizes[1];

    k_zero <<<(N + 255) / 256, 256>>>(N);
    k_deg  <<<(E + 255) / 256, 256>>>(src, dst, E);
    k_scan <<<1, 1024>>>(N);
    k_place<<<(E + 255) / 256, 256>>>(src, dst, E);
    k_isqrt<<<(N + 255) / 256, 256>>>(N);
    k_w12  <<<(INF_ * NF + 63) / 64, 64>>>(W1, W2, b1);
    k_gemm <<<(N + GEMM_TM - 1) / GEMM_TM, 128>>>(X, N);
    k_agg  <<<(N * 10 + 319) / 320, 320>>>(N, 0);
    k_agg  <<<(N * 10 + 319) / 320, 320>>>(N, 1);
    k_final<<<(N + 7) / 8, 256>>>(b2, out, N);
}

// round 3
// speedup vs baseline: 1.7763x; 1.0094x over previous
#include <cuda_runtime.h>

// ---------------------------------------------------------------------------
// SGC linear-collapse + CSR gather aggregation.
//   W12 = W1@W2, cvec = b1@W2
//   Y  = (X*iso) @ W12                      [N,40]
//   Zs[d] = (sum_{e:dst=d} Y[src]) * scale[d],  gsum[d] = sum iso[src]
//   V[d]  =  sum_{e:dst=d} Zs[src]          (scale pre-folded)
//   out = log_softmax( isi*(V + gsum*cvec) + b2 )
// ---------------------------------------------------------------------------

#define MAXN 50048
#define NF   40
#define INF_ 256
#define HID_ 128
#define MAXE 1600000

__device__ int   g_degi_out[MAXN];
__device__ int   g_degi_in [MAXN];
__device__ int   g_cursor  [MAXN];     // doubles as write cursor (starts at rowstart)
__device__ int   g_rowstart[MAXN + 1];
__device__ int   g_tmp     [MAXN];
__device__ int   g_bsum    [64];
__device__ int   g_boff    [64];
__device__ int   g_csr     [MAXE];
__device__ float g_iso     [MAXN];
__device__ float g_isi     [MAXN];
__device__ float g_scale   [MAXN];
__device__ float g_gsum    [MAXN];
__device__ float g_W12     [INF_ * NF];
__device__ float g_cvec    [NF];
__device__ float g_Y[50000 * NF];
__device__ float g_Z[50000 * NF];
__device__ float g_V[50000 * NF];

// ---------------- zero counters -------------------------------------------
__global__ void k_zero(int n) {
    int i = blockIdx.x * blockDim.x + threadIdx.x;
    if (i < n) { g_degi_out[i] = 0; g_degi_in[i] = 0; }
}

// ---------------- degrees (int histogram) ---------------------------------
__global__ void k_deg(const int* __restrict__ src, const int* __restrict__ dst, int E) {
    int e = blockIdx.x * blockDim.x + threadIdx.x;
    if (e >= E) return;
    atomicAdd(&g_degi_out[src[e]], 1);
    atomicAdd(&g_degi_in [dst[e]], 1);
}

// ---------------- scan phase 1: per-block inclusive scan of deg_in ---------
__global__ __launch_bounds__(1024) void k_scan1(int n) {
    __shared__ int wsum[32];
    int t = threadIdx.x, lane = t & 31, wid = t >> 5;
    int i = blockIdx.x * 1024 + t;
    int x = (i < n) ? g_degi_in[i] : 0;
    int v = x;
    #pragma unroll
    for (int d = 1; d < 32; d <<= 1) {
        int u = __shfl_up_sync(0xffffffffu, v, d);
        if (lane >= d) v += u;
    }
    if (lane == 31) wsum[wid] = v;
    __syncthreads();
    if (wid == 0) {
        int w = wsum[lane];
        #pragma unroll
        for (int d = 1; d < 32; d <<= 1) {
            int u = __shfl_up_sync(0xffffffffu, w, d);
            if (lane >= d) w += u;
        }
        wsum[lane] = w;
    }
    __syncthreads();
    int incl = v + (wid > 0 ? wsum[wid - 1] : 0);
    if (i < n) g_tmp[i] = incl;
    if (t == 1023) g_bsum[blockIdx.x] = incl;
}

// ---------------- scan phase 2: scan 49 block sums (1 block) ---------------
__global__ __launch_bounds__(64) void k_scan2(int B) {
    __shared__ int w0tot;
    int t = threadIdx.x, lane = t & 31, wid = t >> 5;
    int x = (t < B) ? g_bsum[t] : 0;
    int v = x;
    #pragma unroll
    for (int d = 1; d < 32; d <<= 1) {
        int u = __shfl_up_sync(0xffffffffu, v, d);
        if (lane >= d) v += u;
    }
    if (wid == 0 && lane == 31) w0tot = v;
    __syncthreads();
    int incl = v + (wid == 1 ? w0tot : 0);
    if (t < B) g_boff[t] = incl - x;   // exclusive
}

// ---------------- scan phase 3: apply offsets + isqrt/scale ----------------
__global__ void k_scan3(int n) {
    int i = blockIdx.x * blockDim.x + threadIdx.x;
    if (i >= n) return;
    int din_i = g_degi_in[i];
    int incl = g_tmp[i] + g_boff[i >> 10];
    g_rowstart[i + 1] = incl;
    g_cursor[i] = incl - din_i;
    if (i == 0) g_rowstart[0] = 0;
    float dout = (float)g_degi_out[i];
    float din  = (float)din_i;
    float iso = dout > 0.f ? rsqrtf(dout) : 0.f;
    float isi = din  > 0.f ? rsqrtf(din)  : 0.f;
    g_iso[i] = iso;
    g_isi[i] = isi;
    g_scale[i] = iso * isi;
}

// ---------------- place edges: 1 random RMW + 1 random write per edge ------
__global__ void k_place(const int* __restrict__ src, const int* __restrict__ dst, int E) {
    int e = blockIdx.x * blockDim.x + threadIdx.x;
    if (e >= E) return;
    int slot = atomicAdd(&g_cursor[dst[e]], 1);
    g_csr[slot] = src[e];
}

// ---------------- W12 = W1 @ W2, cvec = b1 @ W2 ----------------------------
__global__ __launch_bounds__(64) void k_w12(const float* __restrict__ W1,
                                            const float* __restrict__ W2,
                                            const float* __restrict__ b1) {
    int idx = blockIdx.x * 64 + threadIdx.x;
    if (idx < INF_ * NF) {
        int r = idx / NF, c = idx - r * NF;
        const float* w1 = W1 + r * HID_;
        const float* w2 = W2 + c;
        float a0 = 0.f, a1 = 0.f, a2 = 0.f, a3 = 0.f;
        #pragma unroll
        for (int m = 0; m < HID_; m += 4) {
            a0 = fmaf(__ldg(w1 + m + 0), __ldg(w2 + (m + 0) * NF), a0);
            a1 = fmaf(__ldg(w1 + m + 1), __ldg(w2 + (m + 1) * NF), a1);
            a2 = fmaf(__ldg(w1 + m + 2), __ldg(w2 + (m + 2) * NF), a2);
            a3 = fmaf(__ldg(w1 + m + 3), __ldg(w2 + (m + 3) * NF), a3);
        }
        g_W12[idx] = (a0 + a1) + (a2 + a3);
    }
    if (idx < NF) {
        float a0 = 0.f, a1 = 0.f;
        #pragma unroll
        for (int m = 0; m < HID_; m += 2) {
            a0 = fmaf(b1[m], W2[m * NF + idx], a0);
            a1 = fmaf(b1[m + 1], W2[(m + 1) * NF + idx], a1);
        }
        g_cvec[idx] = a0 + a1;
    }
}

// ---------------- Y = (X*iso) @ W12, f32x2, warp-per-colgroup --------------
// 256 threads = 8 warps. Warp w -> cols [5w, 5w+5) (B reads are warp
// broadcasts). Lane l -> rows {l, l+32, l+64, l+96} of the 128-row tile
// (pitch-33 A tile -> conflict-free LDS.32).
#define GEMM_TM 128
#define KT 32
__device__ __forceinline__ unsigned long long pk2(float x, float y) {
    unsigned long long r;
    asm("mov.b64 %0, {%1, %2};" : "=l"(r) : "r"(__float_as_uint(x)), "r"(__float_as_uint(y)));
    return r;
}
__global__ __launch_bounds__(256) void k_gemm(const float* __restrict__ X, int n) {
    __shared__ float  As[GEMM_TM * 33];      // [m][k], pitch 33
    __shared__ float2 Bs2[KT * NF];          // duplicated pairs (b,b)
    const int t    = threadIdx.x;
    const int lane = t & 31;
    const int w    = t >> 5;
    const int c0   = w * 5;
    const int m0   = blockIdx.x * GEMM_TM;

    unsigned long long acc[2][5];
    #pragma unroll
    for (int p = 0; p < 2; p++)
        #pragma unroll
        for (int j = 0; j < 5; j++) acc[p][j] = 0ull;

    for (int k0 = 0; k0 < INF_; k0 += KT) {
        // stage A: 128 rows x 32 k, k fast (coalesced LDG, conflict-free STS)
        #pragma unroll
        for (int i = 0; i < 16; i++) {
            int idx = i * 256 + t;
            int m = idx >> 5;
            int k = idx & 31;
            int row = m0 + m;
            float v = 0.f;
            if (row < n) v = X[row * INF_ + k0 + k] * g_iso[row];
            As[m * 33 + k] = v;
        }
        // stage B: 32 x 40 duplicated pairs
        #pragma unroll
        for (int i = 0; i < 5; i++) {
            int idx = i * 256 + t;
            int k = idx / NF, c = idx - k * NF;
            float wv = g_W12[(k0 + k) * NF + c];
            Bs2[k * NF + c] = make_float2(wv, wv);
        }
        __syncthreads();

        #pragma unroll
        for (int k = 0; k < KT; k++) {
            float a0 = As[(lane      ) * 33 + k];
            float a1 = As[(lane + 32 ) * 33 + k];
            float a2 = As[(lane + 64 ) * 33 + k];
            float a3 = As[(lane + 96 ) * 33 + k];
            unsigned long long pa0 = pk2(a0, a1);
            unsigned long long pa1 = pk2(a2, a3);
            unsigned long long bb[5];
            #pragma unroll
            for (int j = 0; j < 5; j++)
                bb[j] = *(const unsigned long long*)&Bs2[k * NF + c0 + j];
            #pragma unroll
            for (int j = 0; j < 5; j++) {
                asm("fma.rn.f32x2 %0, %1, %2, %3;" : "=l"(acc[0][j]) : "l"(pa0), "l"(bb[j]), "l"(acc[0][j]));
                asm("fma.rn.f32x2 %0, %1, %2, %3;" : "=l"(acc[1][j]) : "l"(pa1), "l"(bb[j]), "l"(acc[1][j]));
            }
        }
        __syncthreads();
    }

    #pragma unroll
    for (int p = 0; p < 2; p++) {
        int r_lo = m0 + lane + 64 * p;       // lo = row lane+64p, hi = +32
        #pragma unroll
        for (int j = 0; j < 5; j++) {
            unsigned int lo, hi;
            asm("mov.b64 {%0, %1}, %2;" : "=r"(lo), "=r"(hi) : "l"(acc[p][j]));
            if (r_lo < n)      g_Y[r_lo * NF + c0 + j]        = __uint_as_float(lo);
            if (r_lo + 32 < n) g_Y[(r_lo + 32) * NF + c0 + j] = __uint_as_float(hi);
        }
    }
}

// ---------------- CSR gather aggregation (10 threads/node, float4 each) ----
// mode 0: Zs[d] = (sum Y[src]) * scale[d],  gsum[d] = sum iso[src]
// mode 1: V[d]  =  sum Zs[src]
__global__ __launch_bounds__(320) void k_agg(int n, int mode) {
    int idx = blockIdx.x * blockDim.x + threadIdx.x;
    int node = idx / 10;
    int q = idx - node * 10;
    if (node >= n) return;
    int beg = g_rowstart[node];
    int end = g_rowstart[node + 1];
    const float* fin = (mode == 0) ? g_Y : g_Z;

    float4 acc0 = make_float4(0.f, 0.f, 0.f, 0.f);
    float4 acc1 = make_float4(0.f, 0.f, 0.f, 0.f);
    float gs0 = 0.f, gs1 = 0.f;
    int e = beg;

    for (; e + 4 <= end; e += 4) {
        int s0 = g_csr[e], s1 = g_csr[e + 1], s2 = g_csr[e + 2], s3 = g_csr[e + 3];
        float4 v0 = *(const float4*)(fin + s0 * NF + q * 4);
        float4 v1 = *(const float4*)(fin + s1 * NF + q * 4);
        float4 v2 = *(const float4*)(fin + s2 * NF + q * 4);
        float4 v3 = *(const float4*)(fin + s3 * NF + q * 4);
        acc0.x += v0.x + v2.x; acc0.y += v0.y + v2.y; acc0.z += v0.z + v2.z; acc0.w += v0.w + v2.w;
        acc1.x += v1.x + v3.x; acc1.y += v1.y + v3.y; acc1.z += v1.z + v3.z; acc1.w += v1.w + v3.w;
        if (mode == 0 && q == 0) { gs0 += g_iso[s0] + g_iso[s2]; gs1 += g_iso[s1] + g_iso[s3]; }
    }
    for (; e < end; e++) {
        int s = g_csr[e];
        float4 v = *(const float4*)(fin + s * NF + q * 4);
        acc0.x += v.x; acc0.y += v.y; acc0.z += v.z; acc0.w += v.w;
        if (mode == 0 && q == 0) gs0 += g_iso[s];
    }
    float4 r = make_float4(acc0.x + acc1.x, acc0.y + acc1.y,
                           acc0.z + acc1.z, acc0.w + acc1.w);
    if (mode == 0) {
        float sc = g_scale[node];
        r.x *= sc; r.y *= sc; r.z *= sc; r.w *= sc;
        if (q == 0) g_gsum[node] = gs0 + gs1;
        *(float4*)(g_Z + node * NF + q * 4) = r;
    } else {
        *(float4*)(g_V + node * NF + q * 4) = r;
    }
}

// ---------------- final: bias + rank-1 b1 term + log_softmax ---------------
__global__ void k_final(const float* __restrict__ b2, float* __restrict__ out, int n) {
    int warp = (blockIdx.x * blockDim.x + threadIdx.x) >> 5;
    int lane = threadIdx.x & 31;
    if (warp >= n) return;
    float isi = g_isi[warp];
    float gs  = g_gsum[warp];
    const float NEG_INF = __int_as_float(0xff800000u);

    int c2 = lane + 32;
    float v1 = isi * g_V[warp * NF + lane] + isi * gs * g_cvec[lane] + b2[lane];
    float v2 = NEG_INF;
    if (c2 < NF)
        v2 = isi * g_V[warp * NF + c2] + isi * gs * g_cvec[c2] + b2[c2];

    float m = fmaxf(v1, v2);
    #pragma unroll
    for (int o = 16; o; o >>= 1) m = fmaxf(m, __shfl_xor_sync(0xffffffffu, m, o));

    float ssum = expf(v1 - m) + ((c2 < NF) ? expf(v2 - m) : 0.f);
    #pragma unroll
    for (int o = 16; o; o >>= 1) ssum += __shfl_xor_sync(0xffffffffu, ssum, o);

    float l = m + logf(ssum);
    out[warp * NF + lane] = v1 - l;
    if (c2 < NF) out[warp * NF + c2] = v2 - l;
}

// ---------------------------------------------------------------------------
extern "C" void kernel_launch(void* const* d_in, const int* in_sizes, int n_in,
                              void* d_out, int out_size) {
    const float* X   = (const float*)d_in[0];
    const int*   src = (const int*)  d_in[1];
    const int*   dst = (const int*)  d_in[2];
    const float* W1  = (const float*)d_in[3];
    const float* b1  = (const float*)d_in[4];
    const float* W2  = (const float*)d_in[5];
    const float* b2  = (const float*)d_in[6];
    float* out = (float*)d_out;

    const int N = in_sizes[0] / INF_;
    const int E = in_sizes[1];
    const int B = (N + 1023) / 1024;

    k_zero <<<(N + 255) / 256, 256>>>(N);
    k_deg  <<<(E + 255) / 256, 256>>>(src, dst, E);
    k_scan1<<<B, 1024>>>(N);
    k_scan2<<<1, 64>>>(B);
    k_scan3<<<(N + 255) / 256, 256>>>(N);
    k_place<<<(E + 255) / 256, 256>>>(src, dst, E);
    k_w12  <<<(INF_ * NF + 63) / 64, 64>>>(W1, W2, b1);
    k_gemm <<<(N + GEMM_TM - 1) / GEMM_TM, 256>>>(X, N);
    k_agg  <<<(N * 10 + 319) / 320, 320>>>(N, 0);
    k_agg  <<<(N * 10 + 319) / 320, 320>>>(N, 1);
    k_final<<<(N + 7) / 8, 256>>>(b2, out, N);
}

// round 4
// speedup vs baseline: 2.6170x; 1.4733x over previous
#include <cuda_runtime.h>

// ---------------------------------------------------------------------------
// SGC linear-collapse + CSR gather aggregation, fork-join graph:
//   deg -> { w12 -> gemm }  ||  { scan1 -> scan23 -> place }  -> agg0 -> agg1+final
//   W12 = W1@W2, cvec = b1@W2
//   Y  = (X*iso) @ W12                      [N,40]
//   Zs[d] = (sum_{e:dst=d} Y[src]) * scale[d],  gsum[d] = sum iso[src]
//   V[d]  =  sum_{e:dst=d} Zs[src]
//   out = log_softmax( isi*(V + gsum*cvec) + b2 )
// ---------------------------------------------------------------------------

#define MAXN 50048
#define NF   40
#define INF_ 256
#define HID_ 128
#define MAXE 1600000

__device__ int   g_degi_out[MAXN];    // zero-init; reset to 0 by agg0 each run
__device__ int   g_degi_in [MAXN];    // zero-init; reset to 0 by agg0 each run
__device__ int   g_cursor  [MAXN];
__device__ int   g_rowstart[MAXN + 1];
__device__ int   g_tmp     [MAXN];
__device__ int   g_bsum    [64];
__device__ int   g_csr     [MAXE];
__device__ float g_iso     [MAXN];
__device__ float g_isi     [MAXN];
__device__ float g_scale   [MAXN];
__device__ float g_gsum    [MAXN];
__device__ float g_W12     [INF_ * NF];
__device__ float g_cvec    [NF];
__device__ float g_Y[50000 * NF];
__device__ float g_Z[50000 * NF];

// ---------------- degrees (int histogram) ---------------------------------
__global__ void k_deg(const int* __restrict__ src, const int* __restrict__ dst, int E) {
    int e = blockIdx.x * blockDim.x + threadIdx.x;
    if (e >= E) return;
    atomicAdd(&g_degi_out[src[e]], 1);
    atomicAdd(&g_degi_in [dst[e]], 1);
}

// ---------------- scan phase 1: per-1024-chunk inclusive scan of deg_in ----
__global__ __launch_bounds__(1024) void k_scan1(int n) {
    __shared__ int wsum[32];
    int t = threadIdx.x, lane = t & 31, wid = t >> 5;
    int i = blockIdx.x * 1024 + t;
    int x = (i < n) ? g_degi_in[i] : 0;
    int v = x;
    #pragma unroll
    for (int d = 1; d < 32; d <<= 1) {
        int u = __shfl_up_sync(0xffffffffu, v, d);
        if (lane >= d) v += u;
    }
    if (lane == 31) wsum[wid] = v;
    __syncthreads();
    if (wid == 0) {
        int w = wsum[lane];
        #pragma unroll
        for (int d = 1; d < 32; d <<= 1) {
            int u = __shfl_up_sync(0xffffffffu, w, d);
            if (lane >= d) w += u;
        }
        wsum[lane] = w;
    }
    __syncthreads();
    int incl = v + (wid > 0 ? wsum[wid - 1] : 0);
    if (i < n) g_tmp[i] = incl;
    if (t == 1023) g_bsum[blockIdx.x] = incl;
}

// ---------------- scan phase 2+3 fused: chunk offsets + rowstart/cursor +
//                  iso/isi/scale (256 threads, 256 nodes per block) ---------
__global__ __launch_bounds__(256) void k_scan23(int n, int B) {
    __shared__ int part[2];
    int t = threadIdx.x;
    int chunk = blockIdx.x >> 2;           // 256*4 = 1024 nodes per chunk
    if (t < 64) {
        int v = (t < chunk) ? g_bsum[t] : 0;
        #pragma unroll
        for (int o = 16; o; o >>= 1) v += __shfl_down_sync(0xffffffffu, v, o);
        if ((t & 31) == 0) part[t >> 5] = v;
    }
    __syncthreads();
    int boff = part[0] + part[1];

    int i = blockIdx.x * 256 + t;
    if (i >= n) return;
    int din_i = g_degi_in[i];
    int incl = g_tmp[i] + boff;
    g_rowstart[i + 1] = incl;
    g_cursor[i] = incl - din_i;
    if (i == 0) g_rowstart[0] = 0;
    float dout = (float)g_degi_out[i];
    float din  = (float)din_i;
    float iso = dout > 0.f ? rsqrtf(dout) : 0.f;
    float isi = din  > 0.f ? rsqrtf(din)  : 0.f;
    g_iso[i] = iso;
    g_isi[i] = isi;
    g_scale[i] = iso * isi;
}

// ---------------- place edges: 1 random RMW + 1 random write per edge ------
__global__ void k_place(const int* __restrict__ src, const int* __restrict__ dst, int E) {
    int e = blockIdx.x * blockDim.x + threadIdx.x;
    if (e >= E) return;
    int slot = atomicAdd(&g_cursor[dst[e]], 1);
    g_csr[slot] = src[e];
}

// ---------------- W12 = W1 @ W2, cvec = b1 @ W2 ----------------------------
__global__ __launch_bounds__(64) void k_w12(const float* __restrict__ W1,
                                            const float* __restrict__ W2,
                                            const float* __restrict__ b1) {
    int idx = blockIdx.x * 64 + threadIdx.x;
    if (idx < INF_ * NF) {
        int r = idx / NF, c = idx - r * NF;
        const float* w1 = W1 + r * HID_;
        const float* w2 = W2 + c;
        float a0 = 0.f, a1 = 0.f, a2 = 0.f, a3 = 0.f;
        #pragma unroll
        for (int m = 0; m < HID_; m += 4) {
            a0 = fmaf(__ldg(w1 + m + 0), __ldg(w2 + (m + 0) * NF), a0);
            a1 = fmaf(__ldg(w1 + m + 1), __ldg(w2 + (m + 1) * NF), a1);
            a2 = fmaf(__ldg(w1 + m + 2), __ldg(w2 + (m + 2) * NF), a2);
            a3 = fmaf(__ldg(w1 + m + 3), __ldg(w2 + (m + 3) * NF), a3);
        }
        g_W12[idx] = (a0 + a1) + (a2 + a3);
    }
    if (idx < NF) {
        float a0 = 0.f, a1 = 0.f;
        #pragma unroll
        for (int m = 0; m < HID_; m += 2) {
            a0 = fmaf(b1[m], W2[m * NF + idx], a0);
            a1 = fmaf(b1[m + 1], W2[(m + 1) * NF + idx], a1);
        }
        g_cvec[idx] = a0 + a1;
    }
}

// ---------------- Y = (X*iso) @ W12, f32x2, warp-per-colgroup --------------
// iso computed inline from g_degi_out (no separate isqrt kernel needed).
#define GEMM_TM 128
#define KT 32
__device__ __forceinline__ unsigned long long pk2(float x, float y) {
    unsigned long long r;
    asm("mov.b64 %0, {%1, %2};" : "=l"(r) : "r"(__float_as_uint(x)), "r"(__float_as_uint(y)));
    return r;
}
__global__ __launch_bounds__(256) void k_gemm(const float* __restrict__ X, int n) {
    __shared__ float  As[GEMM_TM * 33];      // [m][k], pitch 33
    __shared__ float2 Bs2[KT * NF];          // duplicated pairs (b,b)
    __shared__ float  iso_s[GEMM_TM];
    const int t    = threadIdx.x;
    const int lane = t & 31;
    const int w    = t >> 5;
    const int c0   = w * 5;
    const int m0   = blockIdx.x * GEMM_TM;

    if (t < GEMM_TM) {
        int row = m0 + t;
        float iso = 0.f;
        if (row < n) {
            float dout = (float)g_degi_out[row];
            iso = dout > 0.f ? rsqrtf(dout) : 0.f;
        }
        iso_s[t] = iso;
    }
    __syncthreads();

    unsigned long long acc[2][5];
    #pragma unroll
    for (int p = 0; p < 2; p++)
        #pragma unroll
        for (int j = 0; j < 5; j++) acc[p][j] = 0ull;

    for (int k0 = 0; k0 < INF_; k0 += KT) {
        #pragma unroll
        for (int i = 0; i < 16; i++) {
            int idx = i * 256 + t;
            int m = idx >> 5;
            int k = idx & 31;
            int row = m0 + m;
            float v = 0.f;
            if (row < n) v = X[row * INF_ + k0 + k] * iso_s[m];
            As[m * 33 + k] = v;
        }
        #pragma unroll
        for (int i = 0; i < 5; i++) {
            int idx = i * 256 + t;
            int k = idx / NF, c = idx - k * NF;
            float wv = g_W12[(k0 + k) * NF + c];
            Bs2[k * NF + c] = make_float2(wv, wv);
        }
        __syncthreads();

        #pragma unroll
        for (int k = 0; k < KT; k++) {
            float a0 = As[(lane      ) * 33 + k];
            float a1 = As[(lane + 32 ) * 33 + k];
            float a2 = As[(lane + 64 ) * 33 + k];
            float a3 = As[(lane + 96 ) * 33 + k];
            unsigned long long pa0 = pk2(a0, a1);
            unsigned long long pa1 = pk2(a2, a3);
            unsigned long long bb[5];
            #pragma unroll
            for (int j = 0; j < 5; j++)
                bb[j] = *(const unsigned long long*)&Bs2[k * NF + c0 + j];
            #pragma unroll
            for (int j = 0; j < 5; j++) {
                asm("fma.rn.f32x2 %0, %1, %2, %3;" : "=l"(acc[0][j]) : "l"(pa0), "l"(bb[j]), "l"(acc[0][j]));
                asm("fma.rn.f32x2 %0, %1, %2, %3;" : "=l"(acc[1][j]) : "l"(pa1), "l"(bb[j]), "l"(acc[1][j]));
            }
        }
        __syncthreads();
    }

    #pragma unroll
    for (int p = 0; p < 2; p++) {
        int r_lo = m0 + lane + 64 * p;
        #pragma unroll
        for (int j = 0; j < 5; j++) {
            unsigned int lo, hi;
            asm("mov.b64 {%0, %1}, %2;" : "=r"(lo), "=r"(hi) : "l"(acc[p][j]));
            if (r_lo < n)      g_Y[r_lo * NF + c0 + j]        = __uint_as_float(lo);
            if (r_lo + 32 < n) g_Y[(r_lo + 32) * NF + c0 + j] = __uint_as_float(hi);
        }
    }
}

// ---------------- agg0: Zs[d] = (sum Y[src])*scale[d], gsum, deg reset -----
__global__ __launch_bounds__(320) void k_agg0(int n) {
    int idx = blockIdx.x * blockDim.x + threadIdx.x;
    int node = idx / 10;
    int q = idx - node * 10;
    if (node >= n) return;
    if (q == 1) { g_degi_out[node] = 0; g_degi_in[node] = 0; }   // reset for next run
    int beg = g_rowstart[node];
    int end = g_rowstart[node + 1];

    float4 acc0 = make_float4(0.f, 0.f, 0.f, 0.f);
    float4 acc1 = make_float4(0.f, 0.f, 0.f, 0.f);
    float gs0 = 0.f, gs1 = 0.f;
    int e = beg;
    for (; e + 4 <= end; e += 4) {
        int s0 = g_csr[e], s1 = g_csr[e + 1], s2 = g_csr[e + 2], s3 = g_csr[e + 3];
        float4 v0 = *(const float4*)(g_Y + s0 * NF + q * 4);
        float4 v1 = *(const float4*)(g_Y + s1 * NF + q * 4);
        float4 v2 = *(const float4*)(g_Y + s2 * NF + q * 4);
        float4 v3 = *(const float4*)(g_Y + s3 * NF + q * 4);
        acc0.x += v0.x + v2.x; acc0.y += v0.y + v2.y; acc0.z += v0.z + v2.z; acc0.w += v0.w + v2.w;
        acc1.x += v1.x + v3.x; acc1.y += v1.y + v3.y; acc1.z += v1.z + v3.z; acc1.w += v1.w + v3.w;
        if (q == 0) { gs0 += g_iso[s0] + g_iso[s2]; gs1 += g_iso[s1] + g_iso[s3]; }
    }
    for (; e < end; e++) {
        int s = g_csr[e];
        float4 v = *(const float4*)(g_Y + s * NF + q * 4);
        acc0.x += v.x; acc0.y += v.y; acc0.z += v.z; acc0.w += v.w;
        if (q == 0) gs0 += g_iso[s];
    }
    float sc = g_scale[node];
    float4 r = make_float4((acc0.x + acc1.x) * sc, (acc0.y + acc1.y) * sc,
                           (acc0.z + acc1.z) * sc, (acc0.w + acc1.w) * sc);
    if (q == 0) g_gsum[node] = gs0 + gs1;
    *(float4*)(g_Z + node * NF + q * 4) = r;
}

// ---------------- agg1 + final fused: V -> smem -> log_softmax -> out ------
// 320 threads = 32 nodes/block (10 threads x float4 per node).
__global__ __launch_bounds__(320) void k_agg1f(const float* __restrict__ b2,
                                               float* __restrict__ out, int n) {
    __shared__ float sV[32][NF];
    __shared__ float s_cvec[NF];
    int t = threadIdx.x;
    int nl = t / 10;
    int q = t - nl * 10;
    int node = blockIdx.x * 32 + nl;
    if (t < NF) s_cvec[t] = g_cvec[t];

    if (node < n) {
        int beg = g_rowstart[node];
        int end = g_rowstart[node + 1];
        float4 acc0 = make_float4(0.f, 0.f, 0.f, 0.f);
        float4 acc1 = make_float4(0.f, 0.f, 0.f, 0.f);
        int e = beg;
        for (; e + 4 <= end; e += 4) {
            int s0 = g_csr[e], s1 = g_csr[e + 1], s2 = g_csr[e + 2], s3 = g_csr[e + 3];
            float4 v0 = *(const float4*)(g_Z + s0 * NF + q * 4);
            float4 v1 = *(const float4*)(g_Z + s1 * NF + q * 4);
            float4 v2 = *(const float4*)(g_Z + s2 * NF + q * 4);
            float4 v3 = *(const float4*)(g_Z + s3 * NF + q * 4);
            acc0.x += v0.x + v2.x; acc0.y += v0.y + v2.y; acc0.z += v0.z + v2.z; acc0.w += v0.w + v2.w;
            acc1.x += v1.x + v3.x; acc1.y += v1.y + v3.y; acc1.z += v1.z + v3.z; acc1.w += v1.w + v3.w;
        }
        for (; e < end; e++) {
            int s = g_csr[e];
            float4 v = *(const float4*)(g_Z + s * NF + q * 4);
            acc0.x += v.x; acc0.y += v.y; acc0.z += v.z; acc0.w += v.w;
        }
        sV[nl][q * 4 + 0] = acc0.x + acc1.x;
        sV[nl][q * 4 + 1] = acc0.y + acc1.y;
        sV[nl][q * 4 + 2] = acc0.z + acc1.z;
        sV[nl][q * 4 + 3] = acc0.w + acc1.w;
    }
    __syncthreads();

    // log_softmax: 10 warps, warp w handles local nodes w, w+10, w+20, w+30
    int lane = t & 31, w = t >> 5;
    for (int l = w; l < 32; l += 10) {
        int nd = blockIdx.x * 32 + l;
        if (nd >= n) continue;
        float isi = g_isi[nd];
        float gs  = g_gsum[nd];
        const float NEG_INF = __int_as_float(0xff800000u);
        int c2 = lane + 32;
        float v1 = isi * sV[l][lane] + isi * gs * s_cvec[lane] + b2[lane];
        float v2 = NEG_INF;
        if (c2 < NF)
            v2 = isi * sV[l][c2] + isi * gs * s_cvec[c2] + b2[c2];
        float m = fmaxf(v1, v2);
        #pragma unroll
        for (int o = 16; o; o >>= 1) m = fmaxf(m, __shfl_xor_sync(0xffffffffu, m, o));
        float ssum = expf(v1 - m) + ((c2 < NF) ? expf(v2 - m) : 0.f);
        #pragma unroll
        for (int o = 16; o; o >>= 1) ssum += __shfl_xor_sync(0xffffffffu, ssum, o);
        float lg = m + logf(ssum);
        out[nd * NF + lane] = v1 - lg;
        if (c2 < NF) out[nd * NF + c2] = v2 - lg;
    }
}

// ---------------------------------------------------------------------------
extern "C" void kernel_launch(void* const* d_in, const int* in_sizes, int n_in,
                              void* d_out, int out_size) {
    const float* X   = (const float*)d_in[0];
    const int*   src = (const int*)  d_in[1];
    const int*   dst = (const int*)  d_in[2];
    const float* W1  = (const float*)d_in[3];
    const float* b1  = (const float*)d_in[4];
    const float* W2  = (const float*)d_in[5];
    const float* b2  = (const float*)d_in[6];
    float* out = (float*)d_out;

    const int N = in_sizes[0] / INF_;
    const int E = in_sizes[1];
    const int B = (N + 1023) / 1024;

    static cudaStream_t sA = nullptr, sB = nullptr;
    static cudaEvent_t ev0 = nullptr, evDeg = nullptr, evA = nullptr, evB = nullptr;
    if (sA == nullptr) {
        cudaStreamCreateWithFlags(&sA, cudaStreamNonBlocking);
        cudaStreamCreateWithFlags(&sB, cudaStreamNonBlocking);
        cudaEventCreateWithFlags(&ev0,  cudaEventDisableTiming);
        cudaEventCreateWithFlags(&evDeg, cudaEventDisableTiming);
        cudaEventCreateWithFlags(&evA,  cudaEventDisableTiming);
        cudaEventCreateWithFlags(&evB,  cudaEventDisableTiming);
    }

    // fork: w12 starts immediately on sA; deg on main stream
    cudaEventRecord(ev0, 0);
    cudaStreamWaitEvent(sA, ev0, 0);
    k_w12<<<(INF_ * NF + 63) / 64, 64, 0, sA>>>(W1, W2, b1);

    k_deg<<<(E + 255) / 256, 256>>>(src, dst, E);
    cudaEventRecord(evDeg, 0);

    // branch A: gemm (needs deg_out for iso + W12)
    cudaStreamWaitEvent(sA, evDeg, 0);
    k_gemm<<<(N + GEMM_TM - 1) / GEMM_TM, 256, 0, sA>>>(X, N);
    cudaEventRecord(evA, sA);

    // branch B: CSR build
    cudaStreamWaitEvent(sB, evDeg, 0);
    k_scan1<<<B, 1024, 0, sB>>>(N);
    k_scan23<<<(N + 255) / 256, 256, 0, sB>>>(N, B);
    k_place<<<(E + 255) / 256, 256, 0, sB>>>(src, dst, E);
    cudaEventRecord(evB, sB);

    // join
    cudaStreamWaitEvent(0, evA, 0);
    cudaStreamWaitEvent(0, evB, 0);
    k_agg0 <<<(N * 10 + 319) / 320, 320>>>(N);
    k_agg1f<<<(N * 10 + 319) / 320, 320>>>(b2, out, N);
}